// round 7
// baseline (speedup 1.0000x reference)
#include <cuda_runtime.h>
#include <cstdint>

#define N      8192
#define NNZv   262144
#define NSEEDS 256
#define SAMP   7372            /* int(N * 0.9) */
#define GRID   592             /* 148 SMs x 4 blocks — fully resident (<=152x4 too) */
#define TPB    256
#define KCH    128             /* chain blocks */
#define NBAR   5

// ---------------- scratch (device globals; zero-init at module load) -------
__device__ int           g_seed0[N];
__device__ int           g_mask1[N];
__device__ int           g_masknodes[N];
__device__ float         g_deg[N];
__device__ int           g_maskidx[N];
__device__ int           g_temnum;
__device__ int           g_keep[NNZv];
__device__ unsigned      g_barCnt[NBAR];
__device__ unsigned      g_barFlag[NBAR];

// ---------------- device-wide sense-reversing barrier ----------------------
// Self-resetting: safe across graph replays (parity flips each use).
__device__ __forceinline__ void dbar(int id, unsigned target) {
    __syncthreads();
    if (threadIdx.x == 0) {
        volatile unsigned* flag = &g_barFlag[id];
        unsigned my = *flag;
        __threadfence();
        unsigned old = atomicAdd(&g_barCnt[id], 1u);
        if (old == target - 1u) {
            g_barCnt[id] = 0u;
            __threadfence();
            *flag = my ^ 1u;
        } else {
            while (*flag == my) __nanosleep(64);
        }
        __threadfence();
    }
    __syncthreads();
}

// ---------------- Threefry-2x32 (exact JAX reference rounds) ---------------
__host__ __device__ __forceinline__ void threefry(uint32_t key0, uint32_t key1,
                                                  uint32_t x0, uint32_t x1,
                                                  uint32_t &o0, uint32_t &o1) {
    uint32_t ks0 = key0, ks1 = key1, ks2 = key0 ^ key1 ^ 0x1BD11BDAu;
    x0 += ks0; x1 += ks1;
#define TF_ROT(v,d) (((v) << (d)) | ((v) >> (32 - (d))))
#define TF_R(r) { x0 += x1; x1 = TF_ROT(x1, r); x1 ^= x0; }
    TF_R(13) TF_R(15) TF_R(26) TF_R(6)   x0 += ks1; x1 += ks2 + 1u;
    TF_R(17) TF_R(29) TF_R(16) TF_R(24)  x0 += ks2; x1 += ks0 + 2u;
    TF_R(13) TF_R(15) TF_R(26) TF_R(6)   x0 += ks0; x1 += ks1 + 3u;
    TF_R(17) TF_R(29) TF_R(16) TF_R(24)  x0 += ks1; x1 += ks2 + 4u;
    TF_R(13) TF_R(15) TF_R(26) TF_R(6)   x0 += ks2; x1 += ks0 + 5u;
    o0 = x0; o1 = x1;
#undef TF_R
#undef TF_ROT
}

__device__ __forceinline__ float bits_to_uniform(uint32_t b) {
    return __uint_as_float((b >> 9) | 0x3F800000u) - 1.0f;
}

// ---------------- the one kernel -------------------------------------------
__global__ void __launch_bounds__(TPB, 4)
k_all(const int* __restrict__ rows, const int* __restrict__ cols,
      const float* __restrict__ comp, const int* __restrict__ seeds,
      float* __restrict__ out,
      uint32_t t0, uint32_t t1,                 // randint lo-bits subkey
      uint32_t a0, uint32_t a1,                 // k2 (uniform u1)
      uint32_t b0, uint32_t b1)                 // k3 (uniform u2)
{
    const int b = blockIdx.x, t = threadIdx.x;
    float* enc = out;
    float* dec = out + (size_t)N * N;

    // ================= chain (blocks 0..KCH-1), hidden under the fill ======
    if (b < KCH) {
        const int i = b * TPB + t;              // 0..32767

        // phase 0: clear scratch (32768 words across 4 arrays)
        if      (i <     N) g_seed0    [i        ] = 0;
        else if (i < 2 * N) g_mask1    [i -     N] = 0;
        else if (i < 3 * N) g_masknodes[i - 2 * N] = 0;
        else                g_deg      [i - 3 * N] = 0.0f;
        dbar(0, KCH);

        // phase 1: seeds + random node sampling
        if (i < NSEEDS) { int s = seeds[i]; g_seed0[s] = 1; g_masknodes[s] = 1; }
        if (i < SAMP) {
            uint32_t x, y; threefry(t0, t1, 0u, (uint32_t)i, x, y);
            g_masknodes[(x ^ y) & (N - 1)] = 1;
        }
        dbar(1, KCH);

        // phase 2: bfs depth-0 — drop seed-incident edges, mark frontier
        for (int e = i; e < NNZv; e += KCH * TPB) {
            int r = rows[e], c = cols[e];
            bool inc = (__ldcg(&g_seed0[r]) | __ldcg(&g_seed0[c])) != 0;
            g_keep[e] = inc ? 0 : 1;
            if (inc) { g_mask1[r] = 1; g_mask1[c] = 1; }
        }
        dbar(2, KCH);

        // phase 3: bfs depth-1 — drop frontier-incident edges; row degrees
        for (int e = i; e < NNZv; e += KCH * TPB) {
            if (!g_keep[e]) continue;
            int r = rows[e], c = cols[e];
            if (__ldcg(&g_mask1[r]) | __ldcg(&g_mask1[c])) { g_keep[e] = 0; continue; }
            atomicAdd(&g_deg[r], comp[(size_t)r * N + c]);
        }
        dbar(3, KCH);

        // phase 4: block 0 compacts mask nodes (256 thr x 32 elems)
        if (b == 0) {
            __shared__ int wsum[8];
            int lane = t & 31, warp = t >> 5;
            int base = t * 32;
            uint32_t bits = 0; int loc = 0;
#pragma unroll
            for (int j = 0; j < 32; j++) {
                int m = (__ldcg(&g_masknodes[base + j]) |
                         __ldcg(&g_mask1    [base + j])) ? 1 : 0;
                bits |= (uint32_t)m << j; loc += m;
            }
            int inc = loc;
#pragma unroll
            for (int off = 1; off < 32; off <<= 1) {
                int v = __shfl_up_sync(0xFFFFFFFFu, inc, off);
                if (lane >= off) inc += v;
            }
            if (lane == 31) wsum[warp] = inc;
            __syncthreads();
            if (t == 0) {
                int s = 0;
#pragma unroll
                for (int k = 0; k < 8; k++) { int v = wsum[k]; wsum[k] = s; s += v; }
                g_temnum = s;
            }
            __syncthreads();
            int pos = wsum[warp] + inc - loc;
#pragma unroll
            for (int j = 0; j < 32; j++)
                if ((bits >> j) & 1u) g_maskidx[pos++] = base + j;
        }
    }

    // ================= fill: all blocks, static contiguous slices ==========
    {
        const size_t Q = (size_t)2 * N * N / 4;           // float4 count
        float4* o4 = (float4*)out;
        size_t s0 = (size_t)b       * Q / GRID;
        size_t e0 = (size_t)(b + 1) * Q / GRID;
        const float4 z = make_float4(0.f, 0.f, 0.f, 0.f);
        for (size_t i = s0 + t; i < e0; i += TPB)
            __stcs(&o4[i], z);
    }
    dbar(4, GRID);

    // ================= scatter: all blocks =================================
    {
        const float tn = (float)__ldcg(&g_temnum);
        const int   nt = GRID * TPB;
        for (int x = b * TPB + t; x < 2 * NNZv; x += nt) {
            if (x < NNZv) {
                if (x < N) {                       // self loops -> dec
                    size_t d = (size_t)x * N + x;
                    dec[d] = comp[d];
                }
                if (__ldcg(&g_keep[x])) {          // kept edges -> enc + dec
                    int r = rows[x], c = cols[x];
                    size_t idx = (size_t)r * N + c;
                    float v = comp[idx];
                    float nr = rsqrtf(__ldcg(&g_deg[r]) + 1e-12f);
                    float nc = rsqrtf(__ldcg(&g_deg[c]) + 1e-12f);
                    enc[idx] = v * nr * nc;
                    dec[idx] = v;
                }
            } else {                               // random mask pairs -> dec
                int e = x - NNZv;
                uint32_t p, q;
                threefry(a0, a1, 0u, (uint32_t)e, p, q);
                float u1 = bits_to_uniform(p ^ q);
                threefry(b0, b1, 0u, (uint32_t)e, p, q);
                float u2 = bits_to_uniform(p ^ q);
                int r = __ldcg(&g_maskidx[(int)floorf(u1 * tn)]);
                int c = __ldcg(&g_maskidx[(int)floorf(u2 * tn)]);
                size_t xi = (size_t)r * N + c;
                size_t yi = (size_t)c * N + r;
                dec[xi] = comp[xi];
                dec[yi] = comp[yi];
            }
        }
    }
}

// ---------------- launch ---------------------------------------------------
extern "C" void kernel_launch(void* const* d_in, const int* in_sizes, int n_in,
                              void* d_out, int out_size) {
    const int*   rows  = (const int*)d_in[0];
    const int*   cols  = (const int*)d_in[1];
    // d_in[2] = adj_values: unused by the reference output
    const int*   seeds = (const int*)d_in[3];
    const float* comp  = (const float*)d_in[4];

    // host-side Threefry key derivation (root key (0,42))
    uint32_t s10, s11, s20, s21, s30, s31, t0u, t1u, tmpa, tmpb;
    threefry(0u, 42u, 0u, 0u, s10, s11);   // k1 = split(root,3)[0]
    threefry(0u, 42u, 0u, 1u, s20, s21);   // k2 (uniform u1)
    threefry(0u, 42u, 0u, 2u, s30, s31);   // k3 (uniform u2)
    threefry(s10, s11, 0u, 0u, tmpa, tmpb);// randint split: hi-bits subkey (unused)
    threefry(s10, s11, 0u, 1u, t0u, t1u);  // randint split: lo-bits subkey
    (void)tmpa; (void)tmpb;

    k_all<<<GRID, TPB>>>(rows, cols, comp, seeds, (float*)d_out,
                         t0u, t1u, s20, s21, s30, s31);
}

// round 10
// speedup vs baseline: 1.2403x; 1.2403x over previous
#include <cuda_runtime.h>
#include <cstdint>

#define N      8192
#define NNZv   262144
#define NSEEDS 256
#define SAMP   7372            /* int(N * 0.9) */

// ---------------- scratch (device globals; no allocation allowed) ----------
struct Scratch {
    int   seed0[N];
    int   mask1[N];
    int   masknodes[N];
    float deg[N];          // 0.0f == all-zero bytes
};
__device__ Scratch       g_s;
__device__ float         g_norm[N];
__device__ int           g_maskidx[N];
__device__ int           g_temnum;
__device__ unsigned char g_keep[NNZv];   // fully written by k_bfs0

// ---------------- Threefry-2x32 (exact JAX reference rounds) ---------------
__host__ __device__ __forceinline__ void threefry(uint32_t key0, uint32_t key1,
                                                  uint32_t x0, uint32_t x1,
                                                  uint32_t &o0, uint32_t &o1) {
    uint32_t ks0 = key0, ks1 = key1, ks2 = key0 ^ key1 ^ 0x1BD11BDAu;
    x0 += ks0; x1 += ks1;
#define TF_ROT(v,d) (((v) << (d)) | ((v) >> (32 - (d))))
#define TF_R(r) { x0 += x1; x1 = TF_ROT(x1, r); x1 ^= x0; }
    TF_R(13) TF_R(15) TF_R(26) TF_R(6)   x0 += ks1; x1 += ks2 + 1u;
    TF_R(17) TF_R(29) TF_R(16) TF_R(24)  x0 += ks2; x1 += ks0 + 2u;
    TF_R(13) TF_R(15) TF_R(26) TF_R(6)   x0 += ks0; x1 += ks1 + 3u;
    TF_R(17) TF_R(29) TF_R(16) TF_R(24)  x0 += ks1; x1 += ks2 + 4u;
    TF_R(13) TF_R(15) TF_R(26) TF_R(6)   x0 += ks2; x1 += ks0 + 5u;
    o0 = x0; o1 = x1;
#undef TF_R
#undef TF_ROT
}

__device__ __forceinline__ float bits_to_uniform(uint32_t b) {
    return __uint_as_float((b >> 9) | 0x3F800000u) - 1.0f;
}

// ---------------- kernels --------------------------------------------------

// grid-stride zero-fill, 16B stores, fully coalesced
#define ZGRID 2048
#define ZTPB  256
__global__ void __launch_bounds__(ZTPB)
k_zero(float4* __restrict__ out, size_t n4) {
    const float4 z = make_float4(0.f, 0.f, 0.f, 0.f);
    size_t stride = (size_t)ZGRID * ZTPB;
    size_t i = (size_t)blockIdx.x * ZTPB + threadIdx.x;
#pragma unroll 4
    for (; i < n4; i += stride)
        out[i] = z;
}

// seeds -> seed0/masknodes ; random node sampling -> masknodes
__global__ void k_seed_samp(const int* __restrict__ seeds, uint32_t t0, uint32_t t1) {
    int i = blockIdx.x * blockDim.x + threadIdx.x;
    if (i < NSEEDS) { int s = seeds[i]; g_s.seed0[s] = 1; g_s.masknodes[s] = 1; }
    if (i < SAMP) {
        uint32_t a, b; threefry(t0, t1, 0u, (uint32_t)i, a, b);
        g_s.masknodes[(a ^ b) & (N - 1)] = 1;
    }
}

// depth-0: incident edges removed; mark both endpoints as next frontier
__global__ void k_bfs0(const int* __restrict__ rows, const int* __restrict__ cols) {
    int e = blockIdx.x * blockDim.x + threadIdx.x;
    if (e >= NNZv) return;
    int r = rows[e], c = cols[e];
    bool inc = (g_s.seed0[r] | g_s.seed0[c]) != 0;
    g_keep[e] = inc ? 0 : 1;
    if (inc) { g_s.mask1[r] = 1; g_s.mask1[c] = 1; }
}

// depth-1: remove edges touching frontier; accumulate row degree for survivors
__global__ void k_bfs1_deg(const int* __restrict__ rows, const int* __restrict__ cols,
                           const float* __restrict__ comp) {
    int e = blockIdx.x * blockDim.x + threadIdx.x;
    if (e >= NNZv) return;
    if (!g_keep[e]) return;
    int r = rows[e], c = cols[e];
    if (g_s.mask1[r] | g_s.mask1[c]) { g_keep[e] = 0; return; }
    atomicAdd(&g_s.deg[r], comp[(size_t)r * N + c]);
}

// fused: norm computation + compacting prefix scan (warp-shuffle version)
__global__ void k_scan_norm() {
    __shared__ int warp_sums[32];
    int t    = threadIdx.x;
    int lane = t & 31;
    int wid  = t >> 5;
    int base = t * 8;

    int bits = 0, loc = 0;
#pragma unroll
    for (int i = 0; i < 8; i++) {
        g_norm[base + i] = rsqrtf(g_s.deg[base + i] + 1e-12f);
        int m = (g_s.masknodes[base + i] | g_s.mask1[base + i]) ? 1 : 0;
        bits |= m << i; loc += m;
    }

    int inc = loc;
#pragma unroll
    for (int off = 1; off < 32; off <<= 1) {
        int v = __shfl_up_sync(0xFFFFFFFFu, inc, off);
        if (lane >= off) inc += v;
    }
    if (lane == 31) warp_sums[wid] = inc;
    __syncthreads();

    if (wid == 0) {
        int v = warp_sums[lane];
        int s = v;
#pragma unroll
        for (int off = 1; off < 32; off <<= 1) {
            int u = __shfl_up_sync(0xFFFFFFFFu, s, off);
            if (lane >= off) s += u;
        }
        warp_sums[lane] = s - v;     // exclusive warp offset
        if (lane == 31) g_temnum = s;
    }
    __syncthreads();

    int pos = warp_sums[wid] + inc - loc;   // global exclusive prefix
#pragma unroll
    for (int i = 0; i < 8; i++)
        if ((bits >> i) & 1) g_maskidx[pos++] = base + i;
}

// fused scatter: [0,NNZ) kept edges + diagonal, [NNZ,2*NNZ) random mask pairs
__global__ void k_scatter(const int* __restrict__ rows, const int* __restrict__ cols,
                          const float* __restrict__ comp,
                          float* __restrict__ enc, float* __restrict__ dec,
                          uint32_t a0, uint32_t a1, uint32_t b0, uint32_t b1) {
    int i = blockIdx.x * blockDim.x + threadIdx.x;
    if (i < NNZv) {
        if (i < N) {
            size_t d = (size_t)i * N + i;
            dec[d] = comp[d];
        }
        if (g_keep[i]) {
            int r = rows[i], c = cols[i];
            size_t idx = (size_t)r * N + c;
            float v = comp[idx];
            enc[idx] = v * g_norm[r] * g_norm[c];
            dec[idx] = v;
        }
    } else {
        int e = i - NNZv;
        float tn = (float)g_temnum;
        uint32_t p, q;
        threefry(a0, a1, 0u, (uint32_t)e, p, q);
        float u1 = bits_to_uniform(p ^ q);
        threefry(b0, b1, 0u, (uint32_t)e, p, q);
        float u2 = bits_to_uniform(p ^ q);
        int r = g_maskidx[(int)floorf(u1 * tn)];
        int c = g_maskidx[(int)floorf(u2 * tn)];
        size_t x = (size_t)r * N + c;
        size_t y = (size_t)c * N + r;
        dec[x] = comp[x];
        dec[y] = comp[y];
    }
}

// ---------------- launch ---------------------------------------------------
extern "C" void kernel_launch(void* const* d_in, const int* in_sizes, int n_in,
                              void* d_out, int out_size) {
    const int*   rows  = (const int*)d_in[0];
    const int*   cols  = (const int*)d_in[1];
    // d_in[2] = adj_values: unused by the reference output
    const int*   seeds = (const int*)d_in[3];
    const float* comp  = (const float*)d_in[4];

    float* enc = (float*)d_out;
    float* dec = enc + (size_t)N * N;

    // -------- lazily-created resources (no device memory; work unchanged)
    // BOTH branches live on explicit non-legacy streams: a legacy-stream
    // launch during capture picks up dependencies on every forked capture
    // stream, which serialized the graph in earlier rounds.
    static cudaStream_t sFill = nullptr, sChain = nullptr;
    static cudaEvent_t  evFork = nullptr, evFill = nullptr, evChain = nullptr;
    static void* scratch_ptr = nullptr;
    if (sFill == nullptr) {
        cudaStreamCreateWithFlags(&sFill,  cudaStreamNonBlocking);
        cudaStreamCreateWithFlags(&sChain, cudaStreamNonBlocking);
        cudaEventCreateWithFlags(&evFork,  cudaEventDisableTiming);
        cudaEventCreateWithFlags(&evFill,  cudaEventDisableTiming);
        cudaEventCreateWithFlags(&evChain, cudaEventDisableTiming);
        cudaGetSymbolAddress(&scratch_ptr, g_s);
    }

    // -------- host-side Threefry key derivation (root key (0,42))
    uint32_t s10, s11, s20, s21, s30, s31, t0u, t1u, tmpa, tmpb;
    threefry(0u, 42u, 0u, 0u, s10, s11);   // k1 = split(root,3)[0]
    threefry(0u, 42u, 0u, 1u, s20, s21);   // k2 (uniform u1)
    threefry(0u, 42u, 0u, 2u, s30, s31);   // k3 (uniform u2)
    threefry(s10, s11, 0u, 0u, tmpa, tmpb);// randint split: hi-bits subkey (unused)
    threefry(s10, s11, 0u, 1u, t0u, t1u);  // randint split: lo-bits subkey
    (void)tmpa; (void)tmpb;

    const int T = 256;

    // ---- fork from the capture-origin (legacy) stream
    cudaEventRecord(evFork, 0);
    cudaStreamWaitEvent(sFill,  evFork, 0);
    cudaStreamWaitEvent(sChain, evFork, 0);

    // ---- branch A (sFill): 512 MB output zero-fill
    size_t n4 = (size_t)out_size >> 2;
    k_zero<<<ZGRID, ZTPB, 0, sFill>>>((float4*)d_out, n4);

    // ---- branch B (sChain): scratch clear -> seeds/samp -> BFS -> scan/norm
    cudaMemsetAsync(scratch_ptr, 0, sizeof(Scratch), sChain);
    k_seed_samp<<<(SAMP + T - 1) / T, T, 0, sChain>>>(seeds, t0u, t1u);
    k_bfs0     <<<NNZv / T, T, 0, sChain>>>(rows, cols);
    k_bfs1_deg <<<NNZv / T, T, 0, sChain>>>(rows, cols, comp);
    k_scan_norm<<<1, 1024, 0, sChain>>>();

    // ---- join both branches back into the origin stream, then scatter
    cudaEventRecord(evFill,  sFill);
    cudaEventRecord(evChain, sChain);
    cudaStreamWaitEvent(0, evFill,  0);
    cudaStreamWaitEvent(0, evChain, 0);

    k_scatter<<<(2 * NNZv) / T, T>>>(rows, cols, comp, enc, dec,
                                     s20, s21, s30, s31);
}

// round 12
// speedup vs baseline: 1.2513x; 1.0089x over previous
#include <cuda_runtime.h>
#include <cstdint>

#define N      8192
#define NNZv   262144
#define NSEEDS 256
#define SAMP   7372            /* int(N * 0.9) */

// ---------------- scratch (device globals; no allocation allowed) ----------
struct Scratch {
    int   seed0[N];
    int   mask1[N];
    int   masknodes[N];
    float deg[N];          // 0.0f == all-zero bytes
};
__device__ Scratch       g_s;
__device__ float         g_norm[N];
__device__ int           g_maskidx[N];
__device__ int           g_temnum;
__device__ unsigned char g_keep[NNZv];   // fully written by k_bfs0

// ---------------- Threefry-2x32 (exact JAX reference rounds) ---------------
__host__ __device__ __forceinline__ void threefry(uint32_t key0, uint32_t key1,
                                                  uint32_t x0, uint32_t x1,
                                                  uint32_t &o0, uint32_t &o1) {
    uint32_t ks0 = key0, ks1 = key1, ks2 = key0 ^ key1 ^ 0x1BD11BDAu;
    x0 += ks0; x1 += ks1;
#define TF_ROT(v,d) (((v) << (d)) | ((v) >> (32 - (d))))
#define TF_R(r) { x0 += x1; x1 = TF_ROT(x1, r); x1 ^= x0; }
    TF_R(13) TF_R(15) TF_R(26) TF_R(6)   x0 += ks1; x1 += ks2 + 1u;
    TF_R(17) TF_R(29) TF_R(16) TF_R(24)  x0 += ks2; x1 += ks0 + 2u;
    TF_R(13) TF_R(15) TF_R(26) TF_R(6)   x0 += ks0; x1 += ks1 + 3u;
    TF_R(17) TF_R(29) TF_R(16) TF_R(24)  x0 += ks1; x1 += ks2 + 4u;
    TF_R(13) TF_R(15) TF_R(26) TF_R(6)   x0 += ks2; x1 += ks0 + 5u;
    o0 = x0; o1 = x1;
#undef TF_R
#undef TF_ROT
}

__device__ __forceinline__ float bits_to_uniform(uint32_t b) {
    return __uint_as_float((b >> 9) | 0x3F800000u) - 1.0f;
}

// ---------------- kernels --------------------------------------------------

// fast coalesced zero-fill: one float4 per thread (dense block->address
// interleave across SMs — measured 5.4 TB/s vs 4.3 TB/s for grid-stride)
__global__ void k_zero(float4* __restrict__ out) {
    size_t i = (size_t)blockIdx.x * blockDim.x + threadIdx.x;
    out[i] = make_float4(0.f, 0.f, 0.f, 0.f);
}

// seeds -> seed0/masknodes ; random node sampling -> masknodes
__global__ void k_seed_samp(const int* __restrict__ seeds, uint32_t t0, uint32_t t1) {
    int i = blockIdx.x * blockDim.x + threadIdx.x;
    if (i < NSEEDS) { int s = seeds[i]; g_s.seed0[s] = 1; g_s.masknodes[s] = 1; }
    if (i < SAMP) {
        uint32_t a, b; threefry(t0, t1, 0u, (uint32_t)i, a, b);
        g_s.masknodes[(a ^ b) & (N - 1)] = 1;
    }
}

// depth-0: incident edges removed; mark both endpoints as next frontier
__global__ void k_bfs0(const int* __restrict__ rows, const int* __restrict__ cols) {
    int e = blockIdx.x * blockDim.x + threadIdx.x;
    if (e >= NNZv) return;
    int r = rows[e], c = cols[e];
    bool inc = (g_s.seed0[r] | g_s.seed0[c]) != 0;
    g_keep[e] = inc ? 0 : 1;
    if (inc) { g_s.mask1[r] = 1; g_s.mask1[c] = 1; }
}

// depth-1: remove edges touching frontier; accumulate row degree for survivors
__global__ void k_bfs1_deg(const int* __restrict__ rows, const int* __restrict__ cols,
                           const float* __restrict__ comp) {
    int e = blockIdx.x * blockDim.x + threadIdx.x;
    if (e >= NNZv) return;
    if (!g_keep[e]) return;
    int r = rows[e], c = cols[e];
    if (g_s.mask1[r] | g_s.mask1[c]) { g_keep[e] = 0; return; }
    atomicAdd(&g_s.deg[r], comp[(size_t)r * N + c]);
}

// fused: norm computation + compacting prefix scan (warp-shuffle)
__global__ void k_scan_norm() {
    __shared__ int warp_sums[32];
    int t    = threadIdx.x;
    int lane = t & 31;
    int wid  = t >> 5;
    int base = t * 8;

    int bits = 0, loc = 0;
#pragma unroll
    for (int i = 0; i < 8; i++) {
        g_norm[base + i] = rsqrtf(g_s.deg[base + i] + 1e-12f);
        int m = (g_s.masknodes[base + i] | g_s.mask1[base + i]) ? 1 : 0;
        bits |= m << i; loc += m;
    }

    int inc = loc;
#pragma unroll
    for (int off = 1; off < 32; off <<= 1) {
        int v = __shfl_up_sync(0xFFFFFFFFu, inc, off);
        if (lane >= off) inc += v;
    }
    if (lane == 31) warp_sums[wid] = inc;
    __syncthreads();

    if (wid == 0) {
        int v = warp_sums[lane];
        int s = v;
#pragma unroll
        for (int off = 1; off < 32; off <<= 1) {
            int u = __shfl_up_sync(0xFFFFFFFFu, s, off);
            if (lane >= off) s += u;
        }
        warp_sums[lane] = s - v;     // exclusive warp offset
        if (lane == 31) g_temnum = s;
    }
    __syncthreads();

    int pos = warp_sums[wid] + inc - loc;   // global exclusive prefix
#pragma unroll
    for (int i = 0; i < 8; i++)
        if ((bits >> i) & 1) g_maskidx[pos++] = base + i;
}

// enc scatter: kept edges only (runs concurrently with the dec-half fill)
__global__ void k_scatter_enc(const int* __restrict__ rows, const int* __restrict__ cols,
                              const float* __restrict__ comp,
                              float* __restrict__ enc) {
    int e = blockIdx.x * blockDim.x + threadIdx.x;
    if (e >= NNZv || !g_keep[e]) return;
    int r = rows[e], c = cols[e];
    size_t idx = (size_t)r * N + c;
    enc[idx] = comp[idx] * g_norm[r] * g_norm[c];
}

// dec scatter: [0,NNZ) kept edges + diagonal, [NNZ,2*NNZ) random mask pairs
__global__ void k_scatter_dec(const int* __restrict__ rows, const int* __restrict__ cols,
                              const float* __restrict__ comp,
                              float* __restrict__ dec,
                              uint32_t a0, uint32_t a1, uint32_t b0, uint32_t b1) {
    int i = blockIdx.x * blockDim.x + threadIdx.x;
    if (i < NNZv) {
        if (i < N) {
            size_t d = (size_t)i * N + i;
            dec[d] = comp[d];
        }
        if (g_keep[i]) {
            int r = rows[i], c = cols[i];
            size_t idx = (size_t)r * N + c;
            dec[idx] = comp[idx];
        }
    } else {
        int e = i - NNZv;
        float tn = (float)g_temnum;
        uint32_t p, q;
        threefry(a0, a1, 0u, (uint32_t)e, p, q);
        float u1 = bits_to_uniform(p ^ q);
        threefry(b0, b1, 0u, (uint32_t)e, p, q);
        float u2 = bits_to_uniform(p ^ q);
        int r = g_maskidx[(int)floorf(u1 * tn)];
        int c = g_maskidx[(int)floorf(u2 * tn)];
        size_t x = (size_t)r * N + c;
        size_t y = (size_t)c * N + r;
        dec[x] = comp[x];
        dec[y] = comp[y];
    }
}

// ---------------- launch ---------------------------------------------------
extern "C" void kernel_launch(void* const* d_in, const int* in_sizes, int n_in,
                              void* d_out, int out_size) {
    const int*   rows  = (const int*)d_in[0];
    const int*   cols  = (const int*)d_in[1];
    // d_in[2] = adj_values: unused by the reference output
    const int*   seeds = (const int*)d_in[3];
    const float* comp  = (const float*)d_in[4];

    float* enc = (float*)d_out;
    float* dec = enc + (size_t)N * N;

    // -------- lazily-created resources (no device memory; work unchanged)
    static cudaStream_t sFill = nullptr, sChain = nullptr;
    static cudaEvent_t  evFork = nullptr, evEnc = nullptr,
                        evDec = nullptr, evChain = nullptr;
    static void* scratch_ptr = nullptr;
    if (sFill == nullptr) {
        cudaStreamCreateWithFlags(&sFill,  cudaStreamNonBlocking);
        cudaStreamCreateWithFlags(&sChain, cudaStreamNonBlocking);
        cudaEventCreateWithFlags(&evFork,  cudaEventDisableTiming);
        cudaEventCreateWithFlags(&evEnc,   cudaEventDisableTiming);
        cudaEventCreateWithFlags(&evDec,   cudaEventDisableTiming);
        cudaEventCreateWithFlags(&evChain, cudaEventDisableTiming);
        cudaGetSymbolAddress(&scratch_ptr, g_s);
    }

    // -------- host-side Threefry key derivation (root key (0,42))
    uint32_t s10, s11, s20, s21, s30, s31, t0u, t1u, tmpa, tmpb;
    threefry(0u, 42u, 0u, 0u, s10, s11);   // k1 = split(root,3)[0]
    threefry(0u, 42u, 0u, 1u, s20, s21);   // k2 (uniform u1)
    threefry(0u, 42u, 0u, 2u, s30, s31);   // k3 (uniform u2)
    threefry(s10, s11, 0u, 0u, tmpa, tmpb);// randint split: hi-bits subkey (unused)
    threefry(s10, s11, 0u, 1u, t0u, t1u);  // randint split: lo-bits subkey
    (void)tmpa; (void)tmpb;

    const int T = 256;
    const int HALF4 = (N / 4) * N;         // float4 count per half = 16,777,216

    // ---- fork from the capture-origin stream
    cudaEventRecord(evFork, 0);
    cudaStreamWaitEvent(sFill,  evFork, 0);
    cudaStreamWaitEvent(sChain, evFork, 0);

    // ---- branch A (sFill): enc-half fill, then dec-half fill
    k_zero<<<HALF4 / T, T, 0, sFill>>>((float4*)enc);
    cudaEventRecord(evEnc, sFill);
    k_zero<<<HALF4 / T, T, 0, sFill>>>((float4*)dec);
    cudaEventRecord(evDec, sFill);

    // ---- branch B (sChain): chain, then enc scatter (hidden under dec fill)
    cudaMemsetAsync(scratch_ptr, 0, sizeof(Scratch), sChain);
    k_seed_samp<<<(SAMP + T - 1) / T, T, 0, sChain>>>(seeds, t0u, t1u);
    k_bfs0     <<<NNZv / T, T, 0, sChain>>>(rows, cols);
    k_bfs1_deg <<<NNZv / T, T, 0, sChain>>>(rows, cols, comp);
    k_scan_norm<<<1, 1024, 0, sChain>>>();
    cudaStreamWaitEvent(sChain, evEnc, 0);
    k_scatter_enc<<<NNZv / T, T, 0, sChain>>>(rows, cols, comp, enc);
    cudaEventRecord(evChain, sChain);

    // ---- join: dec scatter needs dec fill + chain
    cudaStreamWaitEvent(0, evDec,   0);
    cudaStreamWaitEvent(0, evChain, 0);
    k_scatter_dec<<<(2 * NNZv) / T, T>>>(rows, cols, comp, dec,
                                         s20, s21, s30, s31);
}

// round 13
// speedup vs baseline: 1.3327x; 1.0650x over previous
#include <cuda_runtime.h>
#include <cstdint>

#define N      8192
#define NNZv   262144
#define NSEEDS 256
#define SAMP   7372            /* int(N * 0.9) */

// ---------------- scratch (device globals; no allocation allowed) ----------
struct Scratch {
    int   seed0[N];
    int   mask1[N];
    int   masknodes[N];
    float deg[N];          // 0.0f == all-zero bytes
};
__device__ Scratch       g_s;
__device__ float         g_norm[N];
__device__ int           g_maskidx[N];
__device__ int           g_temnum;
__device__ unsigned char g_keep[NNZv];   // fully written by k_bfs0

// ---------------- Threefry-2x32 (exact JAX reference rounds) ---------------
__host__ __device__ __forceinline__ void threefry(uint32_t key0, uint32_t key1,
                                                  uint32_t x0, uint32_t x1,
                                                  uint32_t &o0, uint32_t &o1) {
    uint32_t ks0 = key0, ks1 = key1, ks2 = key0 ^ key1 ^ 0x1BD11BDAu;
    x0 += ks0; x1 += ks1;
#define TF_ROT(v,d) (((v) << (d)) | ((v) >> (32 - (d))))
#define TF_R(r) { x0 += x1; x1 = TF_ROT(x1, r); x1 ^= x0; }
    TF_R(13) TF_R(15) TF_R(26) TF_R(6)   x0 += ks1; x1 += ks2 + 1u;
    TF_R(17) TF_R(29) TF_R(16) TF_R(24)  x0 += ks2; x1 += ks0 + 2u;
    TF_R(13) TF_R(15) TF_R(26) TF_R(6)   x0 += ks0; x1 += ks1 + 3u;
    TF_R(17) TF_R(29) TF_R(16) TF_R(24)  x0 += ks1; x1 += ks2 + 4u;
    TF_R(13) TF_R(15) TF_R(26) TF_R(6)   x0 += ks2; x1 += ks0 + 5u;
    o0 = x0; o1 = x1;
#undef TF_R
#undef TF_ROT
}

__device__ __forceinline__ float bits_to_uniform(uint32_t b) {
    return __uint_as_float((b >> 9) | 0x3F800000u) - 1.0f;
}

// ---------------- TMA bulk-store zero fill ---------------------------------
// Each block: zero a 16 KB SMEM buffer once, then TMA-bulk-store 16 chunks of
// 16 KB to its contiguous 256 KB slice. Write path = TMA engine (UTMASTG),
// bypassing per-thread STG issue and the L1 store path entirely.
#define ZTPB    128
#define ZGRID   1024           /* per half: 1024 * 256KB = 256 MB */
#define ZCHUNK  16384          /* bytes per bulk store */
#define ZCHUNKS 16             /* chunks per block */

__global__ void __launch_bounds__(ZTPB)
k_zero_tma(char* __restrict__ out) {
    __shared__ __align__(128) float4 buf[ZCHUNK / 16];   // 16 KB
    int t = threadIdx.x;
    const float4 z = make_float4(0.f, 0.f, 0.f, 0.f);
#pragma unroll
    for (int i = t; i < ZCHUNK / 16; i += ZTPB)
        buf[i] = z;
    __syncthreads();

    if (t == 0) {
        // generic -> async-proxy ordering for the SMEM zeroes
        asm volatile("fence.proxy.async.shared::cta;" ::: "memory");
        uint32_t saddr;
        asm("{ .reg .u64 tmp; cvta.to.shared.u64 tmp, %1; cvt.u32.u64 %0, tmp; }"
            : "=r"(saddr) : "l"(buf));
        char* base = out + (size_t)blockIdx.x * (ZCHUNK * ZCHUNKS);
#pragma unroll
        for (int k = 0; k < ZCHUNKS; k++) {
            asm volatile(
                "cp.async.bulk.global.shared::cta.bulk_group [%0], [%1], %2;"
                :: "l"(base + (size_t)k * ZCHUNK), "r"(saddr), "n"(ZCHUNK)
                : "memory");
            asm volatile("cp.async.bulk.commit_group;" ::: "memory");
        }
        // all bulk stores complete (writes visible) before block exit
        asm volatile("cp.async.bulk.wait_group 0;" ::: "memory");
    }
    __syncthreads();
}

// ---------------- chain kernels --------------------------------------------

__global__ void k_seed_samp(const int* __restrict__ seeds, uint32_t t0, uint32_t t1) {
    int i = blockIdx.x * blockDim.x + threadIdx.x;
    if (i < NSEEDS) { int s = seeds[i]; g_s.seed0[s] = 1; g_s.masknodes[s] = 1; }
    if (i < SAMP) {
        uint32_t a, b; threefry(t0, t1, 0u, (uint32_t)i, a, b);
        g_s.masknodes[(a ^ b) & (N - 1)] = 1;
    }
}

__global__ void k_bfs0(const int* __restrict__ rows, const int* __restrict__ cols) {
    int e = blockIdx.x * blockDim.x + threadIdx.x;
    if (e >= NNZv) return;
    int r = rows[e], c = cols[e];
    bool inc = (g_s.seed0[r] | g_s.seed0[c]) != 0;
    g_keep[e] = inc ? 0 : 1;
    if (inc) { g_s.mask1[r] = 1; g_s.mask1[c] = 1; }
}

__global__ void k_bfs1_deg(const int* __restrict__ rows, const int* __restrict__ cols,
                           const float* __restrict__ comp) {
    int e = blockIdx.x * blockDim.x + threadIdx.x;
    if (e >= NNZv) return;
    if (!g_keep[e]) return;
    int r = rows[e], c = cols[e];
    if (g_s.mask1[r] | g_s.mask1[c]) { g_keep[e] = 0; return; }
    atomicAdd(&g_s.deg[r], comp[(size_t)r * N + c]);
}

__global__ void k_scan_norm() {
    __shared__ int warp_sums[32];
    int t    = threadIdx.x;
    int lane = t & 31;
    int wid  = t >> 5;
    int base = t * 8;

    int bits = 0, loc = 0;
#pragma unroll
    for (int i = 0; i < 8; i++) {
        g_norm[base + i] = rsqrtf(g_s.deg[base + i] + 1e-12f);
        int m = (g_s.masknodes[base + i] | g_s.mask1[base + i]) ? 1 : 0;
        bits |= m << i; loc += m;
    }

    int inc = loc;
#pragma unroll
    for (int off = 1; off < 32; off <<= 1) {
        int v = __shfl_up_sync(0xFFFFFFFFu, inc, off);
        if (lane >= off) inc += v;
    }
    if (lane == 31) warp_sums[wid] = inc;
    __syncthreads();

    if (wid == 0) {
        int v = warp_sums[lane];
        int s = v;
#pragma unroll
        for (int off = 1; off < 32; off <<= 1) {
            int u = __shfl_up_sync(0xFFFFFFFFu, s, off);
            if (lane >= off) s += u;
        }
        warp_sums[lane] = s - v;     // exclusive warp offset
        if (lane == 31) g_temnum = s;
    }
    __syncthreads();

    int pos = warp_sums[wid] + inc - loc;
#pragma unroll
    for (int i = 0; i < 8; i++)
        if ((bits >> i) & 1) g_maskidx[pos++] = base + i;
}

// enc scatter: kept edges only (runs concurrently with the dec-half fill)
__global__ void k_scatter_enc(const int* __restrict__ rows, const int* __restrict__ cols,
                              const float* __restrict__ comp,
                              float* __restrict__ enc) {
    int e = blockIdx.x * blockDim.x + threadIdx.x;
    if (e >= NNZv || !g_keep[e]) return;
    int r = rows[e], c = cols[e];
    size_t idx = (size_t)r * N + c;
    enc[idx] = comp[idx] * g_norm[r] * g_norm[c];
}

// dec scatter: [0,NNZ) kept edges + diagonal, [NNZ,2*NNZ) random mask pairs
__global__ void k_scatter_dec(const int* __restrict__ rows, const int* __restrict__ cols,
                              const float* __restrict__ comp,
                              float* __restrict__ dec,
                              uint32_t a0, uint32_t a1, uint32_t b0, uint32_t b1) {
    int i = blockIdx.x * blockDim.x + threadIdx.x;
    if (i < NNZv) {
        if (i < N) {
            size_t d = (size_t)i * N + i;
            dec[d] = comp[d];
        }
        if (g_keep[i]) {
            int r = rows[i], c = cols[i];
            size_t idx = (size_t)r * N + c;
            dec[idx] = comp[idx];
        }
    } else {
        int e = i - NNZv;
        float tn = (float)g_temnum;
        uint32_t p, q;
        threefry(a0, a1, 0u, (uint32_t)e, p, q);
        float u1 = bits_to_uniform(p ^ q);
        threefry(b0, b1, 0u, (uint32_t)e, p, q);
        float u2 = bits_to_uniform(p ^ q);
        int r = g_maskidx[(int)floorf(u1 * tn)];
        int c = g_maskidx[(int)floorf(u2 * tn)];
        size_t x = (size_t)r * N + c;
        size_t y = (size_t)c * N + r;
        dec[x] = comp[x];
        dec[y] = comp[y];
    }
}

// ---------------- launch ---------------------------------------------------
extern "C" void kernel_launch(void* const* d_in, const int* in_sizes, int n_in,
                              void* d_out, int out_size) {
    const int*   rows  = (const int*)d_in[0];
    const int*   cols  = (const int*)d_in[1];
    // d_in[2] = adj_values: unused by the reference output
    const int*   seeds = (const int*)d_in[3];
    const float* comp  = (const float*)d_in[4];

    float* enc = (float*)d_out;
    float* dec = enc + (size_t)N * N;

    // -------- lazily-created resources (no device memory; work unchanged)
    static cudaStream_t sFill = nullptr, sChain = nullptr;
    static cudaEvent_t  evFork = nullptr, evEnc = nullptr,
                        evDec = nullptr, evChain = nullptr;
    static void* scratch_ptr = nullptr;
    if (sFill == nullptr) {
        cudaStreamCreateWithFlags(&sFill,  cudaStreamNonBlocking);
        cudaStreamCreateWithFlags(&sChain, cudaStreamNonBlocking);
        cudaEventCreateWithFlags(&evFork,  cudaEventDisableTiming);
        cudaEventCreateWithFlags(&evEnc,   cudaEventDisableTiming);
        cudaEventCreateWithFlags(&evDec,   cudaEventDisableTiming);
        cudaEventCreateWithFlags(&evChain, cudaEventDisableTiming);
        cudaGetSymbolAddress(&scratch_ptr, g_s);
    }

    // -------- host-side Threefry key derivation (root key (0,42))
    uint32_t s10, s11, s20, s21, s30, s31, t0u, t1u, tmpa, tmpb;
    threefry(0u, 42u, 0u, 0u, s10, s11);   // k1 = split(root,3)[0]
    threefry(0u, 42u, 0u, 1u, s20, s21);   // k2 (uniform u1)
    threefry(0u, 42u, 0u, 2u, s30, s31);   // k3 (uniform u2)
    threefry(s10, s11, 0u, 0u, tmpa, tmpb);// randint split: hi-bits subkey (unused)
    threefry(s10, s11, 0u, 1u, t0u, t1u);  // randint split: lo-bits subkey
    (void)tmpa; (void)tmpb;

    const int T = 256;

    // ---- fork from the capture-origin stream
    cudaEventRecord(evFork, 0);
    cudaStreamWaitEvent(sFill,  evFork, 0);
    cudaStreamWaitEvent(sChain, evFork, 0);

    // ---- branch A (sFill): TMA bulk-store fill, enc half then dec half
    k_zero_tma<<<ZGRID, ZTPB, 0, sFill>>>((char*)enc);
    cudaEventRecord(evEnc, sFill);
    k_zero_tma<<<ZGRID, ZTPB, 0, sFill>>>((char*)dec);
    cudaEventRecord(evDec, sFill);

    // ---- branch B (sChain): chain, then enc scatter (hidden under dec fill)
    cudaMemsetAsync(scratch_ptr, 0, sizeof(Scratch), sChain);
    k_seed_samp<<<(SAMP + T - 1) / T, T, 0, sChain>>>(seeds, t0u, t1u);
    k_bfs0     <<<NNZv / T, T, 0, sChain>>>(rows, cols);
    k_bfs1_deg <<<NNZv / T, T, 0, sChain>>>(rows, cols, comp);
    k_scan_norm<<<1, 1024, 0, sChain>>>();
    cudaStreamWaitEvent(sChain, evEnc, 0);
    k_scatter_enc<<<NNZv / T, T, 0, sChain>>>(rows, cols, comp, enc);
    cudaEventRecord(evChain, sChain);

    // ---- join: dec scatter needs dec fill + chain
    cudaStreamWaitEvent(0, evDec,   0);
    cudaStreamWaitEvent(0, evChain, 0);
    k_scatter_dec<<<(2 * NNZv) / T, T>>>(rows, cols, comp, dec,
                                         s20, s21, s30, s31);
}